// round 4
// baseline (speedup 1.0000x reference)
#include <cuda_runtime.h>
#include <math.h>

// ---------------------------------------------------------------------------
// Problem constants (shapes are fixed by the dataset)
// ---------------------------------------------------------------------------
#define MAXN 50000
#define MAXE 800000

// ---------------------------------------------------------------------------
// Device scratch (static allocation; no cudaMalloc allowed)
// ---------------------------------------------------------------------------
__device__ float g_m1[MAXN * 128];
__device__ float g_q [MAXN * 128];
__device__ float g_p [MAXN * 128];
__device__ float g_m2[MAXN * 128];
__device__ float g_q2[MAXN * 64];
__device__ float g_p2[MAXN * 64];
__device__ int   g_counts[MAXN];
__device__ int   g_offs  [MAXN + 1];
__device__ int   g_cursor[MAXN];
__device__ int   g_csrsrc[MAXE];

// ---------------------------------------------------------------------------
// f32x2 packed-math helpers (Blackwell sm_100+ PTX; ptxas won't auto-fuse)
// ---------------------------------------------------------------------------
__device__ __forceinline__ unsigned long long dup2(float x) {
    unsigned long long r;
    asm("mov.b64 %0, {%1, %1};" : "=l"(r) : "r"(__float_as_uint(x)));
    return r;
}
__device__ __forceinline__ unsigned long long fma2(unsigned long long a,
                                                   unsigned long long b,
                                                   unsigned long long c) {
    unsigned long long d;
    asm("fma.rn.f32x2 %0, %1, %2, %3;" : "=l"(d) : "l"(a), "l"(b), "l"(c));
    return d;
}
__device__ __forceinline__ float2 unpk(unsigned long long v) {
    unsigned int lo, hi;
    asm("mov.b64 {%0, %1}, %2;" : "=r"(lo), "=r"(hi) : "l"(v));
    return make_float2(__uint_as_float(lo), __uint_as_float(hi));
}

__device__ __forceinline__ float gelu_erf(float x) {
    return 0.5f * x * (1.0f + erff(x * 0.70710678118654752440f));
}

// ---------------------------------------------------------------------------
// GEMM: C[M,Nc] = act(A[M,128] @ W[128,Nc] + bias), K fixed = 128.
// Tile 128x64, 256 threads, 8x4 micro-tile, f32x2 packed FMAs (rows paired).
// ---------------------------------------------------------------------------
__global__ __launch_bounds__(256) void gemm_kernel(
    const float* __restrict__ A, const float* __restrict__ W,
    const float* __restrict__ bias, float* __restrict__ C,
    int M, int Nc, int act)
{
    __shared__ __align__(16) float As[32][128];   // As[k][m] (transposed)
    __shared__ __align__(16) float Bs[32][64];    // Bs[k][n]

    const int tid  = threadIdx.x;
    const int brow = blockIdx.x * 128;
    const int bcol = blockIdx.y * 64;
    const int tm   = (tid >> 4) << 3;   // 0..120 step 8
    const int tn   = (tid & 15) << 2;   // 0..60  step 4

    unsigned long long acc[4][4];
#pragma unroll
    for (int i = 0; i < 4; i++)
#pragma unroll
        for (int j = 0; j < 4; j++) acc[i][j] = 0ull;

    // A staging map: thread -> (row, 16-col half)
    const int aRow  = tid >> 1;
    const int aHalf = (tid & 1) << 4;       // 0 or 16
    const int gRow  = brow + aRow;
    const bool aValid = (gRow < M);

    // B staging map: thread -> two consecutive float4 within a 32x64 chunk
    const int bIdx = tid << 1;              // float4 index (0..511)
    const int bk   = bIdx >> 4;             // 0..31
    const int bc   = (bIdx & 15) << 2;      // 0..56, multiple of 8

    for (int kc = 0; kc < 128; kc += 32) {
#pragma unroll
        for (int v = 0; v < 4; v++) {
            float4 t = aValid
                ? *(const float4*)(A + (size_t)gRow * 128 + kc + aHalf + v * 4)
                : make_float4(0.f, 0.f, 0.f, 0.f);
            As[aHalf + v * 4 + 0][aRow] = t.x;
            As[aHalf + v * 4 + 1][aRow] = t.y;
            As[aHalf + v * 4 + 2][aRow] = t.z;
            As[aHalf + v * 4 + 3][aRow] = t.w;
        }
        {
            const float* wp = W + (size_t)(kc + bk) * Nc + bcol + bc;
            float4 t0 = *(const float4*)(wp);
            float4 t1 = *(const float4*)(wp + 4);
            *(float4*)&Bs[bk][bc]     = t0;
            *(float4*)&Bs[bk][bc + 4] = t1;
        }
        __syncthreads();
#pragma unroll
        for (int k = 0; k < 32; k++) {
            ulonglong2 a01 = *(const ulonglong2*)&As[k][tm];
            ulonglong2 a23 = *(const ulonglong2*)&As[k][tm + 4];
            float4 b = *(const float4*)&Bs[k][tn];
            unsigned long long ap[4] = { a01.x, a01.y, a23.x, a23.y };
            unsigned long long bd[4] = { dup2(b.x), dup2(b.y), dup2(b.z), dup2(b.w) };
#pragma unroll
            for (int i = 0; i < 4; i++)
#pragma unroll
                for (int j = 0; j < 4; j++)
                    acc[i][j] = fma2(ap[i], bd[j], acc[i][j]);
        }
        __syncthreads();
    }

#pragma unroll
    for (int j = 0; j < 4; j++) {
        const int col = bcol + tn + j;
        const float bv = bias[col];
#pragma unroll
        for (int i = 0; i < 4; i++) {
            float2 v = unpk(acc[i][j]);
            const int r0 = brow + tm + 2 * i;
            float x0 = v.x + bv;
            float x1 = v.y + bv;
            if (act) { x0 = gelu_erf(x0); x1 = gelu_erf(x1); }
            if (r0 < M)     C[(size_t)r0 * Nc + col]       = x0;
            if (r0 + 1 < M) C[(size_t)(r0 + 1) * Nc + col] = x1;
        }
    }
}

// ---------------------------------------------------------------------------
// CSR build by destination node
// ---------------------------------------------------------------------------
__global__ void zero_kernel(int* __restrict__ a, int n) {
    int i = blockIdx.x * blockDim.x + threadIdx.x;
    if (i < n) a[i] = 0;
}

__global__ void count_kernel(const int* __restrict__ dst, int* __restrict__ counts, int E) {
    int i = blockIdx.x * blockDim.x + threadIdx.x;
    if (i < E) atomicAdd(&counts[dst[i]], 1);
}

__global__ void scan_kernel(const int* __restrict__ counts, int* __restrict__ offs,
                            int* __restrict__ cursor, int n)
{
    __shared__ int sh[1024];
    __shared__ int s_carry;
    const int t = threadIdx.x;
    if (t == 0) { s_carry = 0; offs[0] = 0; }
    __syncthreads();
    for (int base = 0; base < n; base += 1024) {
        const int i = base + t;
        const int v = (i < n) ? counts[i] : 0;
        sh[t] = v;
        __syncthreads();
        for (int o = 1; o < 1024; o <<= 1) {
            int tv = (t >= o) ? sh[t - o] : 0;
            __syncthreads();
            sh[t] += tv;
            __syncthreads();
        }
        const int incl = sh[t] + s_carry;
        if (i < n) { offs[i + 1] = incl; cursor[i] = incl - v; }
        __syncthreads();
        if (t == 1023) s_carry = incl;
        __syncthreads();
    }
}

__global__ void scatter_kernel(const int* __restrict__ src, const int* __restrict__ dst,
                               int* __restrict__ cursor, int* __restrict__ csrsrc, int E)
{
    int i = blockIdx.x * blockDim.x + threadIdx.x;
    if (i < E) {
        int pos = atomicAdd(&cursor[dst[i]], 1);
        csrsrc[pos] = src[i];
    }
}

// ---------------------------------------------------------------------------
// Fused GAT edge softmax + aggregation, one warp per dst node, no atomics.
//   s_e = sum_d leaky(q[dst]+p[src]) * a_d ; es = exp(s) ;
//   agg[dst] = sum_e es * p[src] / sum_e es
// MODE 0: out = gelu(agg + bias)   (layer 1, bias = bg2)
// MODE 1: out = agg + bias         (layer 2, bias = b_out)
// ---------------------------------------------------------------------------
template <int D, int MODE>
__global__ __launch_bounds__(256) void gat_agg_kernel(
    const float* __restrict__ q, const float* __restrict__ p,
    const float* __restrict__ avec, const float* __restrict__ bias,
    const int* __restrict__ offs, const int* __restrict__ csrsrc,
    float* __restrict__ out, int n)
{
    const int node = blockIdx.x * 8 + (threadIdx.x >> 5);
    if (node >= n) return;
    const int lane = threadIdx.x & 31;
    constexpr int V = D / 32;

    float qv[V], av[V], acc[V];
#pragma unroll
    for (int i = 0; i < V; i++) {
        qv[i]  = q[(size_t)node * D + lane * V + i];
        av[i]  = avec[lane * V + i];
        acc[i] = 0.f;
    }
    float denom = 0.f;

    const int s0 = offs[node];
    const int s1 = offs[node + 1];
    for (int j = s0; j < s1; j++) {
        const int s = csrsrc[j];
        float pv[V];
        if constexpr (V == 4) {
            float4 t = *(const float4*)(p + (size_t)s * D + lane * 4);
            pv[0] = t.x; pv[1] = t.y; pv[2] = t.z; pv[3] = t.w;
        } else {
            float2 t = *(const float2*)(p + (size_t)s * D + lane * 2);
            pv[0] = t.x; pv[1] = t.y;
        }
        float part = 0.f;
#pragma unroll
        for (int i = 0; i < V; i++) {
            float u = qv[i] + pv[i];
            u = (u > 0.f) ? u : 0.2f * u;
            part = fmaf(u, av[i], part);
        }
#pragma unroll
        for (int o = 16; o > 0; o >>= 1)
            part += __shfl_xor_sync(0xffffffffu, part, o);
        const float es = __expf(part);
        denom += es;
#pragma unroll
        for (int i = 0; i < V; i++) acc[i] = fmaf(es, pv[i], acc[i]);
    }

    const float inv = (s1 > s0) ? (1.0f / denom) : 0.f;
#pragma unroll
    for (int i = 0; i < V; i++) {
        const int c = lane * V + i;
        float v = acc[i] * inv + bias[c];
        if (MODE == 0) v = gelu_erf(v);
        out[(size_t)node * D + c] = v;
    }
}

// ---------------------------------------------------------------------------
// Host launcher
// ---------------------------------------------------------------------------
static void* sym_addr(const void* s) {
    void* p = nullptr;
    cudaGetSymbolAddress(&p, s);
    return p;
}

extern "C" void kernel_launch(void* const* d_in, const int* in_sizes, int n_in,
                              void* d_out, int out_size)
{
    const float* x    = (const float*)d_in[0];
    const float* W0   = (const float*)d_in[1];
    const float* b0   = (const float*)d_in[2];
    const float* Wq1  = (const float*)d_in[3];
    const float* bq1  = (const float*)d_in[4];
    const float* Wp1  = (const float*)d_in[5];
    const float* bp1  = (const float*)d_in[6];
    const float* a1   = (const float*)d_in[7];
    const float* bg2  = (const float*)d_in[8];
    const float* Wq2  = (const float*)d_in[9];
    const float* bq2  = (const float*)d_in[10];
    const float* Wp2  = (const float*)d_in[11];
    const float* bp2  = (const float*)d_in[12];
    const float* a2   = (const float*)d_in[13];
    const float* bout = (const float*)d_in[14];
    const int*   src  = (const int*)d_in[15];
    const int*   dst  = (const int*)d_in[16];

    const int N = in_sizes[0] / 128;
    const int E = in_sizes[15];

    float* m1 = (float*)sym_addr(g_m1);
    float* q  = (float*)sym_addr(g_q);
    float* p  = (float*)sym_addr(g_p);
    float* m2 = (float*)sym_addr(g_m2);
    float* q2 = (float*)sym_addr(g_q2);
    float* p2 = (float*)sym_addr(g_p2);
    int* counts = (int*)sym_addr(g_counts);
    int* offs   = (int*)sym_addr(g_offs);
    int* cursor = (int*)sym_addr(g_cursor);
    int* csrsrc = (int*)sym_addr(g_csrsrc);

    float* out = (float*)d_out;

    const int eb = (E + 255) / 256;
    const int nb = (N + 255) / 256;

    // CSR by dst
    zero_kernel<<<nb, 256>>>(counts, N);
    count_kernel<<<eb, 256>>>(dst, counts, E);
    scan_kernel<<<1, 1024>>>(counts, offs, cursor, N);
    scatter_kernel<<<eb, 256>>>(src, dst, cursor, csrsrc, E);

    const int gm = (N + 127) / 128;

    // Layer 0: m1 = gelu(x @ W0 + b0)
    gemm_kernel<<<dim3(gm, 2), 256>>>(x, W0, b0, m1, N, 128, 1);

    // Layer 1 projections
    gemm_kernel<<<dim3(gm, 2), 256>>>(m1, Wq1, bq1, q, N, 128, 0);
    gemm_kernel<<<dim3(gm, 2), 256>>>(m1, Wp1, bp1, p, N, 128, 0);

    // Layer 1 edge softmax + aggregation, fused epilogue m2 = gelu(h1 + bg2)
    gat_agg_kernel<128, 0><<<(N + 7) / 8, 256>>>(q, p, a1, bg2, offs, csrsrc, m2, N);

    // Layer 2 projections (D_H=128 -> D_OUT=64)
    gemm_kernel<<<dim3(gm, 1), 256>>>(m2, Wq2, bq2, q2, N, 64, 0);
    gemm_kernel<<<dim3(gm, 1), 256>>>(m2, Wp2, bp2, p2, N, 64, 0);

    // Layer 2 edge softmax + aggregation, fused epilogue out = h2 + b_out
    gat_agg_kernel<64, 1><<<(N + 7) / 8, 256>>>(q2, p2, a2, bout, offs, csrsrc, out, N);

    (void)n_in; (void)out_size;
}

// round 6
// speedup vs baseline: 1.5419x; 1.5419x over previous
#include <cuda_runtime.h>
#include <cuda_bf16.h>
#include <math.h>
#include <stdint.h>

// ---------------------------------------------------------------------------
// Problem constants
// ---------------------------------------------------------------------------
#define MAXN 50000
#define MAXE 800000

// ---------------------------------------------------------------------------
// Device scratch (static; no cudaMalloc allowed)
// ---------------------------------------------------------------------------
__device__ float g_m1[MAXN * 128];
__device__ float g_q [MAXN * 128];
__device__ float g_p [MAXN * 128];
__device__ float g_m2[MAXN * 128];
__device__ float g_q2[MAXN * 64];
__device__ float g_p2[MAXN * 64];
__device__ int   g_counts[MAXN];
__device__ int   g_offs  [MAXN + 1];
__device__ int   g_cursor[MAXN];
__device__ int   g_csrsrc[MAXE];
__device__ int   g_partials[64];
// Pre-packed B operands in per-lane HMMA fragment order (hi / lo images).
// Entry count = (NC/8 nfrags) * 8 ksteps * 32 lanes.
__device__ uint2 g_b0h[4096], g_b0l[4096];   // NC=128
__device__ uint2 g_b1h[8192], g_b1l[8192];   // NC=256
__device__ uint2 g_b2h[4096], g_b2l[4096];   // NC=128

__device__ __forceinline__ uint32_t smem_u32(const void* p) {
    uint32_t a;
    asm("{ .reg .u64 t; cvta.to.shared.u64 t, %1; cvt.u32.u64 %0, t; }"
        : "=r"(a) : "l"(p));
    return a;
}

__device__ __forceinline__ float gelu_erf(float x) {
    return 0.5f * x * (1.0f + erff(x * 0.70710678118654752440f));
}

__device__ __forceinline__ uint32_t pack_bf16x2(float a, float b) {
    __nv_bfloat16 ha = __float2bfloat16(a);
    __nv_bfloat16 hb = __float2bfloat16(b);
    return (uint32_t)__bfloat16_as_ushort(ha) |
           ((uint32_t)__bfloat16_as_ushort(hb) << 16);
}

// ---------------------------------------------------------------------------
// B prep: fp32 W[k][n] (cols 0..ncA-1 from Wa, rest from Wb) ->
// per-lane m16n8k16 "col" B fragments, split into bf16 hi and lo images.
// Fragment mapping: lane holds n = n8*8 + lane/4,
//   reg0: k = kstep*16 + (lane%4)*2 + {0,1}; reg1: k += 8.
// ---------------------------------------------------------------------------
__global__ void prep_b_kernel(const float* __restrict__ Wa, const float* __restrict__ Wb,
                              int ncA, int ncB,
                              uint2* __restrict__ packH, uint2* __restrict__ packL)
{
    const int NF = (ncA + ncB) >> 3;
    const int total = NF * 8 * 32;
    const int idx = blockIdx.x * 256 + threadIdx.x;
    if (idx >= total) return;
    const int lane = idx & 31;
    const int rest = idx >> 5;
    const int n8 = rest % NF;
    const int ks = rest / NF;
    const int n = n8 * 8 + (lane >> 2);
    const int k0 = ks * 16 + (lane & 3) * 2;

    float w[4];
#pragma unroll
    for (int i = 0; i < 4; i++) {
        const int k = k0 + (i >> 1) * 8 + (i & 1);
        w[i] = (n < ncA) ? Wa[k * ncA + n] : Wb[k * ncB + (n - ncA)];
    }
    float h[4], l[4];
#pragma unroll
    for (int i = 0; i < 4; i++) {
        h[i] = __bfloat162float(__float2bfloat16(w[i]));
        l[i] = w[i] - h[i];
    }
    packH[idx] = make_uint2(pack_bf16x2(h[0], h[1]), pack_bf16x2(h[2], h[3]));
    packL[idx] = make_uint2(pack_bf16x2(l[0], l[1]), pack_bf16x2(l[2], l[3]));
}

// ---------------------------------------------------------------------------
// HMMA GEMM: C[M, NC] = act(A[M,128] @ W[128,NC] + bias), K = 128.
// fp32 via bf16 split: Ah*Wh + Al*Wh + Ah*Wl.
// CTA: 128 rows x 128 cols (blockIdx.y = column tile). 8 warps: 4 row x 2 col.
// A: converted to hi/lo bf16 SMEM images, 272B row stride (conflict-free
// ldmatrix.x4). B: pre-packed fragments streamed from L2.
// Output split at column HALF into out0 / out1.
// ---------------------------------------------------------------------------
#define A_STRIDE 272
#define A_IMG    (128 * A_STRIDE)   // 34816 bytes per image

template <int NC, int HALF, int ACT>
__global__ void __launch_bounds__(256) gemm_mma_kernel(
    const float* __restrict__ A,
    const uint2* __restrict__ packH, const uint2* __restrict__ packL,
    const float* __restrict__ bias0, const float* __restrict__ bias1,
    float* __restrict__ out0, float* __restrict__ out1, int M)
{
    extern __shared__ __align__(16) unsigned char smem[];
    constexpr int NF = NC >> 3;
    constexpr int H2 = NC - HALF;

    const int tid  = threadIdx.x;
    const int lane = tid & 31;
    const int warp = tid >> 5;
    const int brow = blockIdx.x * 128;
    const int bcol = blockIdx.y * 128;
    const int wRow = (warp & 3) * 32;
    const int wCol = (warp >> 2) * 64;
    const int n8b  = (bcol + wCol) >> 3;

    // ---- Stage A: fp32 -> bf16 hi/lo into padded SMEM ---------------------
    {
        const int row = tid >> 1;
        const int ch  = (tid & 1) * 64;
        const int grow = brow + row;
        const bool ok = (grow < M);
        const float* ap = A + (size_t)grow * 128 + ch;
        unsigned char* sh = smem + row * A_STRIDE + ch * 2;
#pragma unroll
        for (int c = 0; c < 64; c += 4) {
            float4 f = ok ? *(const float4*)(ap + c) : make_float4(0.f, 0.f, 0.f, 0.f);
            float h0 = __bfloat162float(__float2bfloat16(f.x));
            float h1 = __bfloat162float(__float2bfloat16(f.y));
            float h2 = __bfloat162float(__float2bfloat16(f.z));
            float h3 = __bfloat162float(__float2bfloat16(f.w));
            uint2 hv = make_uint2(pack_bf16x2(h0, h1), pack_bf16x2(h2, h3));
            uint2 lv = make_uint2(pack_bf16x2(f.x - h0, f.y - h1),
                                  pack_bf16x2(f.z - h2, f.w - h3));
            *(uint2*)(sh + c * 2)         = hv;
            *(uint2*)(sh + c * 2 + A_IMG) = lv;
        }
    }
    __syncthreads();

    // ---- Mainloop ---------------------------------------------------------
    float acc[2][8][4];
#pragma unroll
    for (int mf = 0; mf < 2; mf++)
#pragma unroll
        for (int nf = 0; nf < 8; nf++)
#pragma unroll
            for (int e = 0; e < 4; e++) acc[mf][nf][e] = 0.f;

    const uint32_t sA = smem_u32(smem);
    const uint32_t lrow = (uint32_t)(lane & 15);
    const uint32_t lcol = (uint32_t)((lane >> 4) * 16);

#pragma unroll
    for (int ks = 0; ks < 8; ks++) {
        uint32_t ah[2][4], al[2][4];
#pragma unroll
        for (int mf = 0; mf < 2; mf++) {
            uint32_t addr = sA + (wRow + mf * 16 + lrow) * A_STRIDE + ks * 32 + lcol;
            asm volatile("ldmatrix.sync.aligned.m8n8.x4.shared.b16 {%0,%1,%2,%3}, [%4];"
                         : "=r"(ah[mf][0]), "=r"(ah[mf][1]), "=r"(ah[mf][2]), "=r"(ah[mf][3])
                         : "r"(addr));
            asm volatile("ldmatrix.sync.aligned.m8n8.x4.shared.b16 {%0,%1,%2,%3}, [%4];"
                         : "=r"(al[mf][0]), "=r"(al[mf][1]), "=r"(al[mf][2]), "=r"(al[mf][3])
                         : "r"(addr + A_IMG));
        }
#pragma unroll
        for (int nf = 0; nf < 8; nf++) {
            const int bi = (ks * NF + n8b + nf) * 32 + lane;
            const uint2 bh = __ldg(packH + bi);
            const uint2 bl = __ldg(packL + bi);
#pragma unroll
            for (int mf = 0; mf < 2; mf++) {
                float* c = acc[mf][nf];
                asm volatile(
                    "mma.sync.aligned.m16n8k16.row.col.f32.bf16.bf16.f32 "
                    "{%0,%1,%2,%3}, {%4,%5,%6,%7}, {%8,%9}, {%0,%1,%2,%3};"
                    : "+f"(c[0]), "+f"(c[1]), "+f"(c[2]), "+f"(c[3])
                    : "r"(ah[mf][0]), "r"(ah[mf][1]), "r"(ah[mf][2]), "r"(ah[mf][3]),
                      "r"(bh.x), "r"(bh.y));
                asm volatile(
                    "mma.sync.aligned.m16n8k16.row.col.f32.bf16.bf16.f32 "
                    "{%0,%1,%2,%3}, {%4,%5,%6,%7}, {%8,%9}, {%0,%1,%2,%3};"
                    : "+f"(c[0]), "+f"(c[1]), "+f"(c[2]), "+f"(c[3])
                    : "r"(al[mf][0]), "r"(al[mf][1]), "r"(al[mf][2]), "r"(al[mf][3]),
                      "r"(bh.x), "r"(bh.y));
                asm volatile(
                    "mma.sync.aligned.m16n8k16.row.col.f32.bf16.bf16.f32 "
                    "{%0,%1,%2,%3}, {%4,%5,%6,%7}, {%8,%9}, {%0,%1,%2,%3};"
                    : "+f"(c[0]), "+f"(c[1]), "+f"(c[2]), "+f"(c[3])
                    : "r"(ah[mf][0]), "r"(ah[mf][1]), "r"(ah[mf][2]), "r"(ah[mf][3]),
                      "r"(bl.x), "r"(bl.y));
            }
        }
    }

    // ---- Epilogue: bias (+gelu), split store ------------------------------
#pragma unroll
    for (int nf = 0; nf < 8; nf++) {
        const int col = bcol + wCol + nf * 8 + (lane & 3) * 2;
        float bv0, bv1;
        if (col < HALF) { bv0 = bias0[col];        bv1 = bias0[col + 1]; }
        else            { bv0 = bias1[col - HALF]; bv1 = bias1[col + 1 - HALF]; }
#pragma unroll
        for (int mf = 0; mf < 2; mf++) {
            const int r0 = brow + wRow + mf * 16 + (lane >> 2);
#pragma unroll
            for (int h = 0; h < 2; h++) {
                const int row = r0 + h * 8;
                if (row < M) {
                    float v0 = acc[mf][nf][h * 2 + 0] + bv0;
                    float v1 = acc[mf][nf][h * 2 + 1] + bv1;
                    if (ACT) { v0 = gelu_erf(v0); v1 = gelu_erf(v1); }
                    float2 v = make_float2(v0, v1);
                    if (col < HALF)
                        *(float2*)(out0 + (size_t)row * HALF + col) = v;
                    else
                        *(float2*)(out1 + (size_t)row * H2 + (col - HALF)) = v;
                }
            }
        }
    }
}

// ---------------------------------------------------------------------------
// CSR build by destination node (count / hierarchical scan / scatter)
// ---------------------------------------------------------------------------
__global__ void zero_kernel(int* __restrict__ a, int n) {
    int i = blockIdx.x * blockDim.x + threadIdx.x;
    if (i < n) a[i] = 0;
}
__global__ void count_kernel(const int* __restrict__ dst, int* __restrict__ counts, int E) {
    int i = blockIdx.x * blockDim.x + threadIdx.x;
    if (i < E) atomicAdd(&counts[dst[i]], 1);
}
__global__ void __launch_bounds__(1024) scan_block_kernel(
    const int* __restrict__ counts, int* __restrict__ offs,
    int* __restrict__ partials, int n)
{
    __shared__ int ws[32];
    const int i = blockIdx.x * 1024 + threadIdx.x;
    const int lane = threadIdx.x & 31, w = threadIdx.x >> 5;
    const int v = (i < n) ? counts[i] : 0;
    int x = v;
#pragma unroll
    for (int o = 1; o < 32; o <<= 1) {
        int y = __shfl_up_sync(0xffffffffu, x, o);
        if (lane >= o) x += y;
    }
    if (lane == 31) ws[w] = x;
    __syncthreads();
    if (w == 0) {
        int s = ws[lane];
#pragma unroll
        for (int o = 1; o < 32; o <<= 1) {
            int y = __shfl_up_sync(0xffffffffu, s, o);
            if (lane >= o) s += y;
        }
        ws[lane] = s;
    }
    __syncthreads();
    const int incl = x + ((w > 0) ? ws[w - 1] : 0);
    if (i < n) offs[i + 1] = incl;                   // pre-partial inclusive
    if (threadIdx.x == 1023) partials[blockIdx.x] = incl;
}
__global__ void __launch_bounds__(1024) scan_partials_kernel(int* __restrict__ partials, int nb)
{
    __shared__ int ws[32];
    const int lane = threadIdx.x & 31, w = threadIdx.x >> 5;
    const int v = (threadIdx.x < nb) ? partials[threadIdx.x] : 0;
    int x = v;
#pragma unroll
    for (int o = 1; o < 32; o <<= 1) {
        int y = __shfl_up_sync(0xffffffffu, x, o);
        if (lane >= o) x += y;
    }
    if (lane == 31) ws[w] = x;
    __syncthreads();
    if (w == 0) {
        int s = ws[lane];
#pragma unroll
        for (int o = 1; o < 32; o <<= 1) {
            int y = __shfl_up_sync(0xffffffffu, s, o);
            if (lane >= o) s += y;
        }
        ws[lane] = s;
    }
    __syncthreads();
    const int incl = x + ((w > 0) ? ws[w - 1] : 0);
    if (threadIdx.x < nb) partials[threadIdx.x] = incl - v;   // exclusive
}
__global__ void scan_finalize_kernel(
    const int* __restrict__ counts, int* __restrict__ offs,
    int* __restrict__ cursor, const int* __restrict__ partials, int n)
{
    int i = blockIdx.x * blockDim.x + threadIdx.x;
    if (i < n) {
        int off = offs[i + 1] + partials[i >> 10];
        offs[i + 1] = off;
        cursor[i]   = off - counts[i];
    }
    if (i == 0) offs[0] = 0;
}
__global__ void scatter_kernel(const int* __restrict__ src, const int* __restrict__ dst,
                               int* __restrict__ cursor, int* __restrict__ csrsrc, int E)
{
    int i = blockIdx.x * blockDim.x + threadIdx.x;
    if (i < E) {
        int pos = atomicAdd(&cursor[dst[i]], 1);
        csrsrc[pos] = src[i];
    }
}

// ---------------------------------------------------------------------------
// Fused GAT edge softmax + aggregation, one warp per dst node, no atomics.
// 2-deep software pipeline on the scattered p[src] loads.
// MODE 0: out = gelu(agg + bias)   MODE 1: out = agg + bias
// ---------------------------------------------------------------------------
template <int D, int MODE>
__global__ __launch_bounds__(256) void gat_agg_kernel(
    const float* __restrict__ q, const float* __restrict__ p,
    const float* __restrict__ avec, const float* __restrict__ bias,
    const int* __restrict__ offs, const int* __restrict__ csrsrc,
    float* __restrict__ out, int n)
{
    const int node = blockIdx.x * 8 + (threadIdx.x >> 5);
    if (node >= n) return;
    const int lane = threadIdx.x & 31;
    constexpr int V = D / 32;

    float qv[V], av[V], acc[V];
#pragma unroll
    for (int i = 0; i < V; i++) {
        qv[i]  = q[(size_t)node * D + lane * V + i];
        av[i]  = avec[lane * V + i];
        acc[i] = 0.f;
    }
    float denom = 0.f;

    const int s0 = offs[node];
    const int s1 = offs[node + 1];

    float pv[V];
    if (s0 < s1) {
        const int s = __ldg(csrsrc + s0);
        if constexpr (V == 4) {
            float4 t = *(const float4*)(p + (size_t)s * D + lane * 4);
            pv[0]=t.x; pv[1]=t.y; pv[2]=t.z; pv[3]=t.w;
        } else {
            float2 t = *(const float2*)(p + (size_t)s * D + lane * 2);
            pv[0]=t.x; pv[1]=t.y;
        }
    }
    for (int j = s0; j < s1; j++) {
        float pn[V];
#pragma unroll
        for (int i = 0; i < V; i++) pn[i] = 0.f;
        if (j + 1 < s1) {                       // prefetch next edge's p row
            const int s = __ldg(csrsrc + j + 1);
            if constexpr (V == 4) {
                float4 t = *(const float4*)(p + (size_t)s * D + lane * 4);
                pn[0]=t.x; pn[1]=t.y; pn[2]=t.z; pn[3]=t.w;
            } else {
                float2 t = *(const float2*)(p + (size_t)s * D + lane * 2);
                pn[0]=t.x; pn[1]=t.y;
            }
        }
        float part = 0.f;
#pragma unroll
        for (int i = 0; i < V; i++) {
            float u = qv[i] + pv[i];
            u = (u > 0.f) ? u : 0.2f * u;
            part = fmaf(u, av[i], part);
        }
#pragma unroll
        for (int o = 16; o > 0; o >>= 1)
            part += __shfl_xor_sync(0xffffffffu, part, o);
        const float es = __expf(part);
        denom += es;
#pragma unroll
        for (int i = 0; i < V; i++) acc[i] = fmaf(es, pv[i], acc[i]);
#pragma unroll
        for (int i = 0; i < V; i++) pv[i] = pn[i];
    }

    const float inv = (s1 > s0) ? (1.0f / denom) : 0.f;
    float ov[V];
#pragma unroll
    for (int i = 0; i < V; i++) {
        float v = acc[i] * inv + bias[lane * V + i];
        if (MODE == 0) v = gelu_erf(v);
        ov[i] = v;
    }
    if constexpr (V == 4)
        *(float4*)(out + (size_t)node * D + lane * 4) = make_float4(ov[0], ov[1], ov[2], ov[3]);
    else
        *(float2*)(out + (size_t)node * D + lane * 2) = make_float2(ov[0], ov[1]);
}

// ---------------------------------------------------------------------------
// Host launcher
// ---------------------------------------------------------------------------
static void* sym_addr(const void* s) {
    void* p = nullptr;
    cudaGetSymbolAddress(&p, s);
    return p;
}

extern "C" void kernel_launch(void* const* d_in, const int* in_sizes, int n_in,
                              void* d_out, int out_size)
{
    const float* x    = (const float*)d_in[0];
    const float* W0   = (const float*)d_in[1];
    const float* b0   = (const float*)d_in[2];
    const float* Wq1  = (const float*)d_in[3];
    const float* bq1  = (const float*)d_in[4];
    const float* Wp1  = (const float*)d_in[5];
    const float* bp1  = (const float*)d_in[6];
    const float* a1   = (const float*)d_in[7];
    const float* bg2  = (const float*)d_in[8];
    const float* Wq2  = (const float*)d_in[9];
    const float* bq2  = (const float*)d_in[10];
    const float* Wp2  = (const float*)d_in[11];
    const float* bp2  = (const float*)d_in[12];
    const float* a2   = (const float*)d_in[13];
    const float* bout = (const float*)d_in[14];
    const int*   src  = (const int*)d_in[15];
    const int*   dst  = (const int*)d_in[16];

    const int N = in_sizes[0] / 128;
    const int E = in_sizes[15];

    float* m1 = (float*)sym_addr(g_m1);
    float* q  = (float*)sym_addr(g_q);
    float* p  = (float*)sym_addr(g_p);
    float* m2 = (float*)sym_addr(g_m2);
    float* q2 = (float*)sym_addr(g_q2);
    float* p2 = (float*)sym_addr(g_p2);
    int* counts   = (int*)sym_addr(g_counts);
    int* offs     = (int*)sym_addr(g_offs);
    int* cursor   = (int*)sym_addr(g_cursor);
    int* csrsrc   = (int*)sym_addr(g_csrsrc);
    int* partials = (int*)sym_addr(g_partials);
    uint2* b0h = (uint2*)sym_addr(g_b0h);
    uint2* b0l = (uint2*)sym_addr(g_b0l);
    uint2* b1h = (uint2*)sym_addr(g_b1h);
    uint2* b1l = (uint2*)sym_addr(g_b1l);
    uint2* b2h = (uint2*)sym_addr(g_b2h);
    uint2* b2l = (uint2*)sym_addr(g_b2l);

    float* out = (float*)d_out;

    // Dynamic SMEM opt-in (2 * 34816 = 69632 bytes > 48KB default)
    constexpr int SMEM = 2 * A_IMG;
    cudaFuncSetAttribute(gemm_mma_kernel<128, 128, 1>,
                         cudaFuncAttributeMaxDynamicSharedMemorySize, SMEM);
    cudaFuncSetAttribute(gemm_mma_kernel<256, 128, 0>,
                         cudaFuncAttributeMaxDynamicSharedMemorySize, SMEM);
    cudaFuncSetAttribute(gemm_mma_kernel<128, 64, 0>,
                         cudaFuncAttributeMaxDynamicSharedMemorySize, SMEM);

    // Weight fragment packing (tiny)
    prep_b_kernel<<<16, 256>>>(W0,  W0,  128, 0,   b0h, b0l);
    prep_b_kernel<<<32, 256>>>(Wq1, Wp1, 128, 128, b1h, b1l);
    prep_b_kernel<<<16, 256>>>(Wq2, Wp2, 64,  64,  b2h, b2l);

    // CSR by dst
    const int eb = (E + 255) / 256;
    const int nb = (N + 255) / 256;
    const int sbk = (N + 1023) / 1024;
    zero_kernel<<<nb, 256>>>(counts, N);
    count_kernel<<<eb, 256>>>(dst, counts, E);
    scan_block_kernel<<<sbk, 1024>>>(counts, offs, partials, N);
    scan_partials_kernel<<<1, 1024>>>(partials, sbk);
    scan_finalize_kernel<<<nb, 256>>>(counts, offs, cursor, partials, N);
    scatter_kernel<<<eb, 256>>>(src, dst, cursor, csrsrc, E);

    const int gm = (N + 127) / 128;

    // Layer 0: m1 = gelu(x @ W0 + b0)
    gemm_mma_kernel<128, 128, 1><<<dim3(gm, 1), 256, SMEM>>>(
        x, b0h, b0l, b0, b0, m1, m1, N);

    // Layer 1 projections fused: [q | p] = m1 @ [Wq1 | Wp1]
    gemm_mma_kernel<256, 128, 0><<<dim3(gm, 2), 256, SMEM>>>(
        m1, b1h, b1l, bq1, bp1, q, p, N);

    // Layer 1 edge softmax + aggregation, epilogue m2 = gelu(h1 + bg2)
    gat_agg_kernel<128, 0><<<(N + 7) / 8, 256>>>(q, p, a1, bg2, offs, csrsrc, m2, N);

    // Layer 2 projections fused: [q2 | p2] = m2 @ [Wq2 | Wp2]
    gemm_mma_kernel<128, 64, 0><<<dim3(gm, 1), 256, SMEM>>>(
        m2, b2h, b2l, bq2, bp2, q2, p2, N);

    // Layer 2 edge softmax + aggregation, epilogue out = h2 + b_out
    gat_agg_kernel<64, 1><<<(N + 7) / 8, 256>>>(q2, p2, a2, bout, offs, csrsrc, out, N);

    (void)n_in; (void)out_size;
}

// round 9
// speedup vs baseline: 1.5928x; 1.0330x over previous
#include <cuda_runtime.h>
#include <cuda_bf16.h>
#include <math.h>
#include <stdint.h>

// ---------------------------------------------------------------------------
// Problem constants
// ---------------------------------------------------------------------------
#define MAXN 50000
#define MAXE 800000

// ---------------------------------------------------------------------------
// Device scratch (static; no cudaMalloc allowed)
// ---------------------------------------------------------------------------
__device__ float g_m1[MAXN * 128];
__device__ float g_q [MAXN * 128];
__device__ float g_p [MAXN * 128];
__device__ float g_m2[MAXN * 128];
__device__ float g_q2[MAXN * 64];
__device__ float g_p2[MAXN * 64];
__device__ int   g_counts[MAXN];
__device__ int   g_offs  [MAXN + 1];
__device__ int   g_cursor[MAXN];
__device__ int   g_csrsrc[MAXE];
__device__ int   g_partials[64];
// Pre-packed B operands in per-lane HMMA fragment order (hi / lo images).
__device__ uint2 g_b0h[4096], g_b0l[4096];   // NC=128
__device__ uint2 g_b1h[8192], g_b1l[8192];   // NC=256
__device__ uint2 g_b2h[4096], g_b2l[4096];   // NC=128

__device__ __forceinline__ uint32_t smem_u32(const void* p) {
    uint32_t a;
    asm("{ .reg .u64 t; cvta.to.shared.u64 t, %1; cvt.u32.u64 %0, t; }"
        : "=r"(a) : "l"(p));
    return a;
}

__device__ __forceinline__ float gelu_erf(float x) {
    return 0.5f * x * (1.0f + erff(x * 0.70710678118654752440f));
}

__device__ __forceinline__ uint32_t pack_bf16x2(float a, float b) {
    __nv_bfloat16 ha = __float2bfloat16(a);
    __nv_bfloat16 hb = __float2bfloat16(b);
    return (uint32_t)__bfloat16_as_ushort(ha) |
           ((uint32_t)__bfloat16_as_ushort(hb) << 16);
}

// ---------------------------------------------------------------------------
// Combined prep: zero the CSR counters AND pack all three weight sets into
// per-lane m16n8k16 "col" B fragments (bf16 hi + lo images) in ONE launch.
// Fragment mapping: lane holds n = n8*8 + lane/4,
//   reg0: k = kstep*16 + (lane%4)*2 + {0,1}; reg1: k += 8.
// ---------------------------------------------------------------------------
__device__ __forceinline__ void prep_one(
    const float* __restrict__ Wa, const float* __restrict__ Wb,
    int ncA, int ncB, uint2* __restrict__ packH, uint2* __restrict__ packL,
    int idx)
{
    const int NF = (ncA + ncB) >> 3;
    const int lane = idx & 31;
    const int rest = idx >> 5;
    const int n8 = rest % NF;
    const int ks = rest / NF;
    const int n = n8 * 8 + (lane >> 2);
    const int k0 = ks * 16 + (lane & 3) * 2;

    float w[4];
#pragma unroll
    for (int i = 0; i < 4; i++) {
        const int k = k0 + (i >> 1) * 8 + (i & 1);
        w[i] = (n < ncA) ? Wa[k * ncA + n] : Wb[k * ncB + (n - ncA)];
    }
    float h[4];
#pragma unroll
    for (int i = 0; i < 4; i++)
        h[i] = __bfloat162float(__float2bfloat16(w[i]));
    packH[idx] = make_uint2(pack_bf16x2(h[0], h[1]), pack_bf16x2(h[2], h[3]));
    packL[idx] = make_uint2(pack_bf16x2(w[0] - h[0], w[1] - h[1]),
                            pack_bf16x2(w[2] - h[2], w[3] - h[3]));
}

__global__ void prep_all_kernel(
    const float* __restrict__ W0,
    const float* __restrict__ Wq1, const float* __restrict__ Wp1,
    const float* __restrict__ Wq2, const float* __restrict__ Wp2,
    uint2* __restrict__ b0h, uint2* __restrict__ b0l,
    uint2* __restrict__ b1h, uint2* __restrict__ b1l,
    uint2* __restrict__ b2h, uint2* __restrict__ b2l,
    int* __restrict__ counts, int n)
{
    const int idx = blockIdx.x * 256 + threadIdx.x;   // 64 blocks -> 16384 threads
    if (idx < 4096)
        prep_one(W0, W0, 128, 0, b0h, b0l, idx);
    else if (idx < 12288)
        prep_one(Wq1, Wp1, 128, 128, b1h, b1l, idx - 4096);
    else if (idx < 16384)
        prep_one(Wq2, Wp2, 64, 64, b2h, b2l, idx - 12288);
    // grid-stride zero of the CSR counters (50000 ints over 16384 threads)
    for (int i = idx; i < n; i += 64 * 256) counts[i] = 0;
}

// ---------------------------------------------------------------------------
// HMMA GEMM: C[M, NC] = act(A[M,128] @ W[128,NC] + bias), K = 128.
// fp32 via bf16 split: Ah*Wh + Al*Wh + Ah*Wl.
// CTA: 128 rows x 128 cols. 8 warps: 4 row x 2 col.
// ---------------------------------------------------------------------------
#define A_STRIDE 272
#define A_IMG    (128 * A_STRIDE)   // 34816 bytes per image

template <int NC, int HALF, int ACT>
__global__ void __launch_bounds__(256) gemm_mma_kernel(
    const float* __restrict__ A,
    const uint2* __restrict__ packH, const uint2* __restrict__ packL,
    const float* __restrict__ bias0, const float* __restrict__ bias1,
    float* __restrict__ out0, float* __restrict__ out1, int M)
{
    extern __shared__ __align__(16) unsigned char smem[];
    constexpr int NF = NC >> 3;
    constexpr int H2 = NC - HALF;

    const int tid  = threadIdx.x;
    const int lane = tid & 31;
    const int warp = tid >> 5;
    const int brow = blockIdx.x * 128;
    const int bcol = blockIdx.y * 128;
    const int wRow = (warp & 3) * 32;
    const int wCol = (warp >> 2) * 64;
    const int n8b  = (bcol + wCol) >> 3;

    // ---- Stage A: fp32 -> bf16 hi/lo into padded SMEM ---------------------
    {
        const int row = tid >> 1;
        const int ch  = (tid & 1) * 64;
        const int grow = brow + row;
        const bool ok = (grow < M);
        const float* ap = A + (size_t)grow * 128 + ch;
        unsigned char* sh = smem + row * A_STRIDE + ch * 2;
#pragma unroll
        for (int c = 0; c < 64; c += 4) {
            float4 f = ok ? *(const float4*)(ap + c) : make_float4(0.f, 0.f, 0.f, 0.f);
            float h0 = __bfloat162float(__float2bfloat16(f.x));
            float h1 = __bfloat162float(__float2bfloat16(f.y));
            float h2 = __bfloat162float(__float2bfloat16(f.z));
            float h3 = __bfloat162float(__float2bfloat16(f.w));
            uint2 hv = make_uint2(pack_bf16x2(h0, h1), pack_bf16x2(h2, h3));
            uint2 lv = make_uint2(pack_bf16x2(f.x - h0, f.y - h1),
                                  pack_bf16x2(f.z - h2, f.w - h3));
            *(uint2*)(sh + c * 2)         = hv;
            *(uint2*)(sh + c * 2 + A_IMG) = lv;
        }
    }
    __syncthreads();

    // ---- Mainloop ---------------------------------------------------------
    float acc[2][8][4];
#pragma unroll
    for (int mf = 0; mf < 2; mf++)
#pragma unroll
        for (int nf = 0; nf < 8; nf++)
#pragma unroll
            for (int e = 0; e < 4; e++) acc[mf][nf][e] = 0.f;

    const uint32_t sA = smem_u32(smem);
    const uint32_t lrow = (uint32_t)(lane & 15);
    const uint32_t lcol = (uint32_t)((lane >> 4) * 16);

#pragma unroll
    for (int ks = 0; ks < 8; ks++) {
        uint32_t ah[2][4], al[2][4];
#pragma unroll
        for (int mf = 0; mf < 2; mf++) {
            uint32_t addr = sA + (wRow + mf * 16 + lrow) * A_STRIDE + ks * 32 + lcol;
            asm volatile("ldmatrix.sync.aligned.m8n8.x4.shared.b16 {%0,%1,%2,%3}, [%4];"
                         : "=r"(ah[mf][0]), "=r"(ah[mf][1]), "=r"(ah[mf][2]), "=r"(ah[mf][3])
                         : "r"(addr));
            asm volatile("ldmatrix.sync.aligned.m8n8.x4.shared.b16 {%0,%1,%2,%3}, [%4];"
                         : "=r"(al[mf][0]), "=r"(al[mf][1]), "=r"(al[mf][2]), "=r"(al[mf][3])
                         : "r"(addr + A_IMG));
        }
#pragma unroll
        for (int nf = 0; nf < 8; nf++) {
            const int bi = (ks * NF + n8b + nf) * 32 + lane;
            const uint2 bh = __ldg(packH + bi);
            const uint2 bl = __ldg(packL + bi);
#pragma unroll
            for (int mf = 0; mf < 2; mf++) {
                float* c = acc[mf][nf];
                asm volatile(
                    "mma.sync.aligned.m16n8k16.row.col.f32.bf16.bf16.f32 "
                    "{%0,%1,%2,%3}, {%4,%5,%6,%7}, {%8,%9}, {%0,%1,%2,%3};"
                    : "+f"(c[0]), "+f"(c[1]), "+f"(c[2]), "+f"(c[3])
                    : "r"(ah[mf][0]), "r"(ah[mf][1]), "r"(ah[mf][2]), "r"(ah[mf][3]),
                      "r"(bh.x), "r"(bh.y));
                asm volatile(
                    "mma.sync.aligned.m16n8k16.row.col.f32.bf16.bf16.f32 "
                    "{%0,%1,%2,%3}, {%4,%5,%6,%7}, {%8,%9}, {%0,%1,%2,%3};"
                    : "+f"(c[0]), "+f"(c[1]), "+f"(c[2]), "+f"(c[3])
                    : "r"(al[mf][0]), "r"(al[mf][1]), "r"(al[mf][2]), "r"(al[mf][3]),
                      "r"(bh.x), "r"(bh.y));
                asm volatile(
                    "mma.sync.aligned.m16n8k16.row.col.f32.bf16.bf16.f32 "
                    "{%0,%1,%2,%3}, {%4,%5,%6,%7}, {%8,%9}, {%0,%1,%2,%3};"
                    : "+f"(c[0]), "+f"(c[1]), "+f"(c[2]), "+f"(c[3])
                    : "r"(ah[mf][0]), "r"(ah[mf][1]), "r"(ah[mf][2]), "r"(ah[mf][3]),
                      "r"(bl.x), "r"(bl.y));
            }
        }
    }

    // ---- Epilogue: bias (+gelu), split store ------------------------------
#pragma unroll
    for (int nf = 0; nf < 8; nf++) {
        const int col = bcol + wCol + nf * 8 + (lane & 3) * 2;
        float bv0, bv1;
        if (col < HALF) { bv0 = bias0[col];        bv1 = bias0[col + 1]; }
        else            { bv0 = bias1[col - HALF]; bv1 = bias1[col + 1 - HALF]; }
#pragma unroll
        for (int mf = 0; mf < 2; mf++) {
            const int r0 = brow + wRow + mf * 16 + (lane >> 2);
#pragma unroll
            for (int h = 0; h < 2; h++) {
                const int row = r0 + h * 8;
                if (row < M) {
                    float v0 = acc[mf][nf][h * 2 + 0] + bv0;
                    float v1 = acc[mf][nf][h * 2 + 1] + bv1;
                    if (ACT) { v0 = gelu_erf(v0); v1 = gelu_erf(v1); }
                    float2 v = make_float2(v0, v1);
                    if (col < HALF)
                        *(float2*)(out0 + (size_t)row * HALF + col) = v;
                    else
                        *(float2*)(out1 + (size_t)row * H2 + (col - HALF)) = v;
                }
            }
        }
    }
}

// ---------------------------------------------------------------------------
// CSR build by destination node (count / hierarchical scan / scatter)
// ---------------------------------------------------------------------------
__global__ void count_kernel(const int* __restrict__ dst, int* __restrict__ counts, int E) {
    int i = blockIdx.x * blockDim.x + threadIdx.x;
    if (i < E) atomicAdd(&counts[dst[i]], 1);
}
__global__ void __launch_bounds__(1024) scan_block_kernel(
    const int* __restrict__ counts, int* __restrict__ offs,
    int* __restrict__ partials, int n)
{
    __shared__ int ws[32];
    const int i = blockIdx.x * 1024 + threadIdx.x;
    const int lane = threadIdx.x & 31, w = threadIdx.x >> 5;
    const int v = (i < n) ? counts[i] : 0;
    int x = v;
#pragma unroll
    for (int o = 1; o < 32; o <<= 1) {
        int y = __shfl_up_sync(0xffffffffu, x, o);
        if (lane >= o) x += y;
    }
    if (lane == 31) ws[w] = x;
    __syncthreads();
    if (w == 0) {
        int s = ws[lane];
#pragma unroll
        for (int o = 1; o < 32; o <<= 1) {
            int y = __shfl_up_sync(0xffffffffu, s, o);
            if (lane >= o) s += y;
        }
        ws[lane] = s;
    }
    __syncthreads();
    const int incl = x + ((w > 0) ? ws[w - 1] : 0);
    if (i < n) offs[i + 1] = incl;                   // pre-partial inclusive
    if (threadIdx.x == 1023) partials[blockIdx.x] = incl;
}
__global__ void __launch_bounds__(1024) scan_partials_kernel(int* __restrict__ partials, int nb)
{
    __shared__ int ws[32];
    const int lane = threadIdx.x & 31, w = threadIdx.x >> 5;
    const int v = (threadIdx.x < nb) ? partials[threadIdx.x] : 0;
    int x = v;
#pragma unroll
    for (int o = 1; o < 32; o <<= 1) {
        int y = __shfl_up_sync(0xffffffffu, x, o);
        if (lane >= o) x += y;
    }
    if (lane == 31) ws[w] = x;
    __syncthreads();
    if (w == 0) {
        int s = ws[lane];
#pragma unroll
        for (int o = 1; o < 32; o <<= 1) {
            int y = __shfl_up_sync(0xffffffffu, s, o);
            if (lane >= o) s += y;
        }
        ws[lane] = s;
    }
    __syncthreads();
    const int incl = x + ((w > 0) ? ws[w - 1] : 0);
    if (threadIdx.x < nb) partials[threadIdx.x] = incl - v;   // exclusive
}
__global__ void scan_finalize_kernel(
    const int* __restrict__ counts, int* __restrict__ offs,
    int* __restrict__ cursor, const int* __restrict__ partials, int n)
{
    int i = blockIdx.x * blockDim.x + threadIdx.x;
    if (i < n) {
        int off = offs[i + 1] + partials[i >> 10];
        offs[i + 1] = off;
        cursor[i]   = off - counts[i];
    }
    if (i == 0) offs[0] = 0;
}
__global__ void scatter_kernel(const int* __restrict__ src, const int* __restrict__ dst,
                               int* __restrict__ cursor, int* __restrict__ csrsrc, int E)
{
    int i = blockIdx.x * blockDim.x + threadIdx.x;
    if (i < E) {
        int pos = atomicAdd(&cursor[dst[i]], 1);
        csrsrc[pos] = src[i];
    }
}

// ---------------------------------------------------------------------------
// Fused GAT edge softmax + aggregation, one warp per dst node, no atomics.
// 4-wide edge unroll: four independent load/reduce/exp chains per iteration
// (MLP=4 on the scattered 512B p-row L2 loads, pipelined shfl trees).
// MODE 0: out = gelu(agg + bias)   MODE 1: out = agg + bias
// ---------------------------------------------------------------------------
template <int D, int MODE>
__global__ __launch_bounds__(256) void gat_agg_kernel(
    const float* __restrict__ q, const float* __restrict__ p,
    const float* __restrict__ avec, const float* __restrict__ bias,
    const int* __restrict__ offs, const int* __restrict__ csrsrc,
    float* __restrict__ out, int n)
{
    const int node = blockIdx.x * 8 + (threadIdx.x >> 5);
    if (node >= n) return;
    const int lane = threadIdx.x & 31;
    constexpr int V = D / 32;

    float qv[V], av[V], acc[V];
#pragma unroll
    for (int i = 0; i < V; i++) {
        qv[i]  = q[(size_t)node * D + lane * V + i];
        av[i]  = avec[lane * V + i];
        acc[i] = 0.f;
    }
    float denom = 0.f;

    const int e0 = offs[node];
    const int e1 = offs[node + 1];

    int j = e0;
    for (; j + 4 <= e1; j += 4) {
        int sidx[4];
#pragma unroll
        for (int u = 0; u < 4; u++) sidx[u] = __ldg(csrsrc + j + u);
        float pv[4][V];
#pragma unroll
        for (int u = 0; u < 4; u++) {
            if constexpr (V == 4) {
                float4 t = *(const float4*)(p + (size_t)sidx[u] * D + lane * 4);
                pv[u][0]=t.x; pv[u][1]=t.y; pv[u][2]=t.z; pv[u][3]=t.w;
            } else {
                float2 t = *(const float2*)(p + (size_t)sidx[u] * D + lane * 2);
                pv[u][0]=t.x; pv[u][1]=t.y;
            }
        }
        float part[4] = {0.f, 0.f, 0.f, 0.f};
#pragma unroll
        for (int i = 0; i < V; i++) {
#pragma unroll
            for (int u = 0; u < 4; u++) {
                float uu = qv[i] + pv[u][i];
                uu = (uu > 0.f) ? uu : 0.2f * uu;
                part[u] = fmaf(uu, av[i], part[u]);
            }
        }
#pragma unroll
        for (int o = 16; o > 0; o >>= 1) {
#pragma unroll
            for (int u = 0; u < 4; u++)
                part[u] += __shfl_xor_sync(0xffffffffu, part[u], o);
        }
        float es[4];
#pragma unroll
        for (int u = 0; u < 4; u++) es[u] = __expf(part[u]);
        denom += (es[0] + es[1]) + (es[2] + es[3]);
#pragma unroll
        for (int i = 0; i < V; i++) {
#pragma unroll
            for (int u = 0; u < 4; u++)
                acc[i] = fmaf(es[u], pv[u][i], acc[i]);
        }
    }
    for (; j < e1; j++) {
        const int s = __ldg(csrsrc + j);
        float pv[V];
        if constexpr (V == 4) {
            float4 t = *(const float4*)(p + (size_t)s * D + lane * 4);
            pv[0]=t.x; pv[1]=t.y; pv[2]=t.z; pv[3]=t.w;
        } else {
            float2 t = *(const float2*)(p + (size_t)s * D + lane * 2);
            pv[0]=t.x; pv[1]=t.y;
        }
        float part = 0.f;
#pragma unroll
        for (int i = 0; i < V; i++) {
            float u = qv[i] + pv[i];
            u = (u > 0.f) ? u : 0.2f * u;
            part = fmaf(u, av[i], part);
        }
#pragma unroll
        for (int o = 16; o > 0; o >>= 1)
            part += __shfl_xor_sync(0xffffffffu, part, o);
        const float es = __expf(part);
        denom += es;
#pragma unroll
        for (int i = 0; i < V; i++) acc[i] = fmaf(es, pv[i], acc[i]);
    }

    const float inv = (e1 > e0) ? (1.0f / denom) : 0.f;
    float ov[V];
#pragma unroll
    for (int i = 0; i < V; i++) {
        float v = acc[i] * inv + bias[lane * V + i];
        if (MODE == 0) v = gelu_erf(v);
        ov[i] = v;
    }
    if constexpr (V == 4)
        *(float4*)(out + (size_t)node * D + lane * 4) = make_float4(ov[0], ov[1], ov[2], ov[3]);
    else
        *(float2*)(out + (size_t)node * D + lane * 2) = make_float2(ov[0], ov[1]);
}

// ---------------------------------------------------------------------------
// Host launcher (single stream — stream/event creation trips the allocation
// guards in this harness; everything stays on the capture stream)
// ---------------------------------------------------------------------------
static void* sym_addr(const void* s) {
    void* p = nullptr;
    cudaGetSymbolAddress(&p, s);
    return p;
}

extern "C" void kernel_launch(void* const* d_in, const int* in_sizes, int n_in,
                              void* d_out, int out_size)
{
    const float* x    = (const float*)d_in[0];
    const float* W0   = (const float*)d_in[1];
    const float* b0   = (const float*)d_in[2];
    const float* Wq1  = (const float*)d_in[3];
    const float* bq1  = (const float*)d_in[4];
    const float* Wp1  = (const float*)d_in[5];
    const float* bp1  = (const float*)d_in[6];
    const float* a1   = (const float*)d_in[7];
    const float* bg2  = (const float*)d_in[8];
    const float* Wq2  = (const float*)d_in[9];
    const float* bq2  = (const float*)d_in[10];
    const float* Wp2  = (const float*)d_in[11];
    const float* bp2  = (const float*)d_in[12];
    const float* a2   = (const float*)d_in[13];
    const float* bout = (const float*)d_in[14];
    const int*   src  = (const int*)d_in[15];
    const int*   dst  = (const int*)d_in[16];

    const int N = in_sizes[0] / 128;
    const int E = in_sizes[15];

    float* m1 = (float*)sym_addr(g_m1);
    float* q  = (float*)sym_addr(g_q);
    float* p  = (float*)sym_addr(g_p);
    float* m2 = (float*)sym_addr(g_m2);
    float* q2 = (float*)sym_addr(g_q2);
    float* p2 = (float*)sym_addr(g_p2);
    int* counts   = (int*)sym_addr(g_counts);
    int* offs     = (int*)sym_addr(g_offs);
    int* cursor   = (int*)sym_addr(g_cursor);
    int* csrsrc   = (int*)sym_addr(g_csrsrc);
    int* partials = (int*)sym_addr(g_partials);
    uint2* b0h = (uint2*)sym_addr(g_b0h);
    uint2* b0l = (uint2*)sym_addr(g_b0l);
    uint2* b1h = (uint2*)sym_addr(g_b1h);
    uint2* b1l = (uint2*)sym_addr(g_b1l);
    uint2* b2h = (uint2*)sym_addr(g_b2h);
    uint2* b2l = (uint2*)sym_addr(g_b2l);

    float* out = (float*)d_out;

    constexpr int SMEM = 2 * A_IMG;   // 69632 bytes
    cudaFuncSetAttribute(gemm_mma_kernel<128, 128, 1>,
                         cudaFuncAttributeMaxDynamicSharedMemorySize, SMEM);
    cudaFuncSetAttribute(gemm_mma_kernel<256, 128, 0>,
                         cudaFuncAttributeMaxDynamicSharedMemorySize, SMEM);
    cudaFuncSetAttribute(gemm_mma_kernel<128, 64, 0>,
                         cudaFuncAttributeMaxDynamicSharedMemorySize, SMEM);

    const int eb  = (E + 255) / 256;
    const int nb  = (N + 255) / 256;
    const int sbk = (N + 1023) / 1024;
    const int gm  = (N + 127) / 128;

    // Prep: weight fragment packing + CSR counter zeroing (one launch)
    prep_all_kernel<<<64, 256>>>(W0, Wq1, Wp1, Wq2, Wp2,
                                 b0h, b0l, b1h, b1l, b2h, b2l, counts, N);

    // CSR by dst
    count_kernel        <<<eb, 256>>>(dst, counts, E);
    scan_block_kernel   <<<sbk, 1024>>>(counts, offs, partials, N);
    scan_partials_kernel<<<1, 1024>>>(partials, sbk);
    scan_finalize_kernel<<<nb, 256>>>(counts, offs, cursor, partials, N);
    scatter_kernel      <<<eb, 256>>>(src, dst, cursor, csrsrc, E);

    // Layer 0: m1 = gelu(x @ W0 + b0)
    gemm_mma_kernel<128, 128, 1><<<dim3(gm, 1), 256, SMEM>>>(
        x, b0h, b0l, b0, b0, m1, m1, N);

    // Layer 1 projections fused: [q | p] = m1 @ [Wq1 | Wp1]
    gemm_mma_kernel<256, 128, 0><<<dim3(gm, 2), 256, SMEM>>>(
        m1, b1h, b1l, bq1, bp1, q, p, N);

    // Layer 1 edge softmax + aggregation, epilogue m2 = gelu(h1 + bg2)
    gat_agg_kernel<128, 0><<<(N + 7) / 8, 256>>>(q, p, a1, bg2, offs, csrsrc, m2, N);

    // Layer 2 projections fused: [q2 | p2] = m2 @ [Wq2 | Wp2]
    gemm_mma_kernel<128, 64, 0><<<dim3(gm, 1), 256, SMEM>>>(
        m2, b2h, b2l, bq2, bp2, q2, p2, N);

    // Layer 2 edge softmax + aggregation, epilogue out = h2 + b_out
    gat_agg_kernel<64, 1><<<(N + 7) / 8, 256>>>(q2, p2, a2, bout, offs, csrsrc, out, N);

    (void)n_in; (void)out_size;
}